// round 6
// baseline (speedup 1.0000x reference)
#include <cuda_runtime.h>

// SphericalBessel, Miller downward recurrence in scaled variable
//   S_l = j_l * (x*sigma)^(-l),  sigma = exact per-thread power of two.
// Branch-free recurrence  S_{l-1} = (2l+1)*sigma*S_l - (x*sigma)^2*S_{l+1},
// double-single (unnormalized pair) arithmetic.
//
// ILP=2: each thread runs TWO independent recurrences (adjacent k = 2s+1,
// 2s+2) interleaved -> two dependency chains per warp hide the 4-cyc FFMA
// latency of the serial DS step; adjacent k makes the epilogue a float2
// STG.64 per l (coalesced 128B per half-warp).
//
// Thread = (n, k-pair). 16 threads per n; warp = 2 n.

#define NPTS   65536
#define KMAX   32
#define LMAX   32
#define LSTART 49   // L_MAX + int(sqrt(10*L_MAX)) = 32 + 17

// a + b and a - b as FFMA with immediate +-1.0 multiplier.
__device__ __forceinline__ float fa(float a, float b) {
    float d; asm("fma.rn.f32 %0,%1,0f3F800000,%2;" : "=f"(d) : "f"(a), "f"(b)); return d;
}
__device__ __forceinline__ float fs(float a, float b) {  // a - b
    float d; asm("fma.rn.f32 %0,%1,0fBF800000,%2;" : "=f"(d) : "f"(b), "f"(a)); return d;
}

__global__ void __launch_bounds__(256)
sph_bessel_ilp2(const float* __restrict__ r, float* __restrict__ out) {
    int tid = blockIdx.x * 256 + threadIdx.x;
    int n   = tid >> 4;
    int sub = tid & 15;                   // k-pair: k = 2*sub+1, 2*sub+2
    float rv = __ldg(&r[n]);

    float xh[2], xl[2], sig[2], zh[2], X2h[2], X2l[2];
    float Ah[2], Al[2], Bh[2], Bl[2];
    float y[2][LMAX];
    float y0[2];

    #pragma unroll
    for (int j = 0; j < 2; ++j) {
        float kf = (float)(2 * sub + 1 + j);
        xh[j] = rv * kf;
        xl[j] = fmaf(rv, kf, -xh[j]);                 // exact DS x = r*k

        // sigma = 0.25 / 2^floor(log2 max(x,99)) via exponent bits (exact pow2)
        float m = fmaxf(xh[j], 99.0f);
        int pb = __float_as_int(m) & 0x7f800000;
        sig[j] = __int_as_float(0x7E000000 - pb);

        // z = x*sigma (exact), X2 = z^2 as DS
        zh[j] = xh[j] * sig[j];
        float zl = xl[j] * sig[j];
        X2h[j] = zh[j] * zh[j];
        float e = fmaf(zh[j], zh[j], -X2h[j]);
        e = fmaf(zh[j], 2.0f * zl, e);
        X2l[j] = fmaf(zl, zl, e);

        Ah[j] = 0x1p70f; Al[j] = 0.0f; Bh[j] = 0.0f; Bl[j] = 0.0f;
    }

    #pragma unroll
    for (int i = LSTART; i >= 1; --i) {
        #pragma unroll
        for (int j = 0; j < 2; ++j) {
            float cs = (float)(2 * i + 1) * sig[j];   // exact (int<=99 * pow2)

            // t = cs (x) A   (DS product, exact residual)
            float th = cs * Ah[j];
            float te = fmaf(cs, Ah[j], -th);
            te = fmaf(cs, Al[j], te);

            // u = X2 (x) B
            float uh = X2h[j] * Bh[j];
            float ue = fmaf(X2h[j], Bh[j], -uh);
            ue = fmaf(X2h[j], Bl[j], ue);
            ue = fmaf(X2l[j], Bh[j], ue);

            // C = t - u : branchless Knuth two-sum of (th, -uh)
            float sh = fs(th, uh);
            float v  = fs(sh, th);
            float w  = fs(sh, v);
            float e1 = fs(th, w);
            float t1 = fa(uh, v);
            float er = fs(e1, t1);
            float lo = fa(er, te);
            lo = fs(lo, ue);

            Bh[j] = Ah[j]; Bl[j] = Al[j];
            Ah[j] = sh;    Al[j] = lo;

            if (i == 1)         y0[j] = fa(sh, lo);   // only y[0] needs DS
            else if (i <= LMAX) y[j][i - 1] = sh;
        }
    }
    y[0][0] = y0[0];
    y[1][0] = y0[1];

    // normalization: true j0 = sin(x)/x (MUFU), x_lo phase compensation.
    float nrm[2];
    #pragma unroll
    for (int j = 0; j < 2; ++j) {
        float kf = (float)(2 * sub + 1 + j);
        float s, cc;
        __sincosf(xh[j], &s, &cc);
        s = fmaf(xl[j], cc, s);
        nrm[j] = __fdividef(s * (0.7978845608028654f * kf), xh[j] * y0[j]);
    }

    // out[n][l][k]: thread owns k = {2sub, 2sub+1} (0-based) -> float2 store.
    float2* o = (float2*)out + (size_t)n * (LMAX * KMAX / 2) + sub;
    #pragma unroll
    for (int l = 0; l < LMAX; ++l) {
        o[(size_t)l * (KMAX / 2)] = make_float2(y[0][l] * nrm[0],
                                                y[1][l] * nrm[1]);
        nrm[0] *= zh[0];                  // uncompensated z^l chain (<=31 ulp)
        nrm[1] *= zh[1];
    }
}

extern "C" void kernel_launch(void* const* d_in, const int* in_sizes, int n_in,
                              void* d_out, int out_size) {
    const float* r = (const float*)d_in[0];
    float* out = (float*)d_out;
    int total = NPTS * KMAX / 2;              // 1,048,576 threads
    sph_bessel_ilp2<<<total / 256, 256>>>(r, out);
}

// round 7
// speedup vs baseline: 1.0416x; 1.0416x over previous
#include <cuda_runtime.h>

// SphericalBessel, Miller downward recurrence in scaled variable
//   S_l = j_l * (x*sigma)^(-l),  sigma = exact per-thread power of two.
// Branch-free recurrence  S_{l-1} = (2l+1)*sigma*S_l - (x*sigma)^2*S_{l+1},
// double-single (unnormalized pair) arithmetic.
//
// R7: y[] tap array lives in SHARED memory (conflict-free [l][tid] layout)
// instead of 32 registers -> regs ~61 -> ~36, occupancy 46% -> ~80%,
// issue efficiency up. Only y0 (feeding the 1/y0-amplified normalization)
// stays in a register at DS-rounded accuracy.
//
// Thread = one (n,k). Warp = one n, k=0..31 -> coalesced 128B stores per l.

#define NPTS   65536
#define KMAX   32
#define LMAX   32
#define LSTART 49   // L_MAX + int(sqrt(10*L_MAX)) = 32 + 17
#define BLK    256

// a + b and a - b as FFMA with immediate +-1.0 multiplier.
__device__ __forceinline__ float fa(float a, float b) {
    float d; asm("fma.rn.f32 %0,%1,0f3F800000,%2;" : "=f"(d) : "f"(a), "f"(b)); return d;
}
__device__ __forceinline__ float fs(float a, float b) {  // a - b
    float d; asm("fma.rn.f32 %0,%1,0fBF800000,%2;" : "=f"(d) : "f"(b), "f"(a)); return d;
}

__global__ void __launch_bounds__(BLK)
sph_bessel_sm(const float* __restrict__ r, float* __restrict__ out) {
    __shared__ float ysm[LMAX][BLK];      // 32KB: taps, conflict-free per warp

    int tid = blockIdx.x * BLK + threadIdx.x;
    int lt  = threadIdx.x;
    int n  = tid >> 5;
    int kk = tid & 31;                    // k = kk+1
    float kf = (float)(kk + 1);
    float rv = __ldg(&r[n]);

    // exact DS x = r*k
    float xh = rv * kf;
    float xl = fmaf(rv, kf, -xh);

    // sigma = 0.25 / 2^floor(log2 max(x,99)) via exponent bits (exact pow2)
    float m = fmaxf(xh, 99.0f);
    int pb = __float_as_int(m) & 0x7f800000;
    float sigma = __int_as_float(0x7E000000 - pb);

    // z = x*sigma (exact), X2 = z^2 as DS
    float zh = xh * sigma, zl = xl * sigma;
    float X2h = zh * zh;
    float X2l = fmaf(zh, zh, -X2h);
    X2l = fmaf(zh, 2.0f * zl, X2l);
    X2l = fmaf(zl, zl, X2l);

    // state: A = S_l, B = S_{l+1}, unnormalized DS pairs. Init (2^70, 0).
    float Ah = 0x1p70f, Al = 0.0f, Bh = 0.0f, Bl = 0.0f;
    float y0 = 0.0f;

    #pragma unroll
    for (int i = LSTART; i >= 1; --i) {
        float cs = (float)(2 * i + 1) * sigma;   // exact (int<=99 * pow2)

        // t = cs (x) A   (DS product, exact residual)
        float th = cs * Ah;
        float te = fmaf(cs, Ah, -th);
        te = fmaf(cs, Al, te);

        // u = X2 (x) B
        float uh = X2h * Bh;
        float ue = fmaf(X2h, Bh, -uh);
        ue = fmaf(X2h, Bl, ue);
        ue = fmaf(X2l, Bh, ue);

        // C = t - u : branchless Knuth two-sum of (th, -uh)
        float sh = fs(th, uh);
        float v  = fs(sh, th);
        float w  = fs(sh, v);
        float e1 = fs(th, w);
        float t1 = fa(uh, v);
        float er = fs(e1, t1);
        float lo = fa(er, te);
        lo = fs(lo, ue);

        Bh = Ah; Bl = Al;
        Ah = sh; Al = lo;

        if (i == 1)         y0 = fa(sh, lo);     // DS-rounded: feeds 1/y0
        else if (i <= LMAX) ysm[i - 1][lt] = sh; // tap: 2^-24 rel is enough
    }

    // normalization: true j0 = sin(x)/x (MUFU), x_lo phase compensation.
    float s, cc;
    __sincosf(xh, &s, &cc);
    s = fmaf(xl, cc, s);
    float norm = __fdividef(s * (0.7978845608028654f * kf), xh * y0);

    float* o = out + (size_t)n * (LMAX * KMAX) + kk;
    o[0] = y0 * norm;                     // l = 0
    norm *= zh;
    #pragma unroll
    for (int l = 1; l < LMAX; ++l) {
        o[(size_t)l * KMAX] = ysm[l][lt] * norm;  // coalesced 128B per l
        norm *= zh;                                // uncompensated z^l chain
    }
}

extern "C" void kernel_launch(void* const* d_in, const int* in_sizes, int n_in,
                              void* d_out, int out_size) {
    const float* r = (const float*)d_in[0];
    float* out = (float*)d_out;
    int total = NPTS * KMAX;                  // 2,097,152 threads
    sph_bessel_sm<<<total / BLK, BLK>>>(r, out);
}